// round 5
// baseline (speedup 1.0000x reference)
#include <cuda_runtime.h>

// Decoder: T_IN=12, B=65536, H=64, T_OUT=12, OVERLAP=3
// One warp processes NB=4 batch elements across all 12 scan steps.
// encoder_out slice lives in registers (24 floats/b/lane), hidden split as
// lane -> dims {lane, lane+32}. GRU matvec uses W_hh staged in SMEM as
// float2-pairs over k, consumed with packed fma.rn.f32x2 (2 MACs/inst).

#define FULLMASK 0xFFFFFFFFu

constexpr int T_IN  = 12;
constexpr int T_OUT = 12;
constexpr int B     = 65536;
constexpr int H     = 64;
constexpr int NB    = 4;             // batch elements per warp
constexpr int WARPS = 4;             // warps per CTA
constexpr int THREADS = WARPS * 32;
constexpr int BPC   = WARPS * NB;    // 16 batch elements per CTA
constexpr int K2    = H / 2;         // 32 k-pairs

// SMEM: W2[k2][192] float2 (48KB) + h staging (WARPS*NB*64 floats = 4KB)
constexpr int W2_ELEMS = K2 * 192;               // 6144 float2
constexpr int SMEM_BYTES = W2_ELEMS * 8 + WARPS * NB * H * 4;

__device__ __forceinline__ void ffma2(unsigned long long& d,
                                      unsigned long long a,
                                      unsigned long long b) {
    asm("fma.rn.f32x2 %0, %1, %2, %0;" : "+l"(d) : "l"(a), "l"(b));
}

__device__ __forceinline__ float f2lo(unsigned long long v) {
    return __uint_as_float((unsigned)(v & 0xFFFFFFFFull));
}
__device__ __forceinline__ float f2hi(unsigned long long v) {
    return __uint_as_float((unsigned)(v >> 32));
}

__device__ __forceinline__ float sigf(float x) {
    return __fdividef(1.0f, 1.0f + __expf(-x));
}
__device__ __forceinline__ float tanhfast(float x) {
    return __fdividef(2.0f, 1.0f + __expf(-2.0f * x)) - 1.0f;
}

__global__ void __launch_bounds__(THREADS)
decoder_kernel(const float* __restrict__ enc,    // (12, B, 64)
               const float* __restrict__ hid0,   // (B, 64)
               const float* __restrict__ last,   // (B, 3)
               const float* __restrict__ Wih,    // (192, 3)
               const float* __restrict__ Whh,    // (192, 64)
               const float* __restrict__ bih,    // (192)
               const float* __restrict__ bhh,    // (192)
               const float* __restrict__ Wlin,   // (1, 64)
               const float* __restrict__ blin,   // (1)
               float* __restrict__ out)          // (B, 12)
{
    extern __shared__ float smem[];
    float2* Wsh = reinterpret_cast<float2*>(smem);
    float*  hsh = smem + 2 * W2_ELEMS;

    const int tid  = threadIdx.x;
    const int lane = tid & 31;
    const int w    = tid >> 5;

    // Stage W_hh into SMEM as k-pairs: Wsh[k2*192 + j] = (W[j][2k2], W[j][2k2+1])
    for (int i = tid; i < W2_ELEMS; i += THREADS) {
        int k2 = i / 192, j = i % 192;
        Wsh[i] = make_float2(__ldg(&Whh[j * 64 + 2 * k2]),
                             __ldg(&Whh[j * 64 + 2 * k2 + 1]));
    }
    __syncthreads();

    const int b0 = blockIdx.x * BPC + w * NB;

    // Per-lane parameters: lane owns rows j = lane + 32*r, r=0..5
    float wih[6][3], vbih[6], vbhh[6];
#pragma unroll
    for (int r = 0; r < 6; r++) {
        int j = lane + 32 * r;
        wih[r][0] = __ldg(&Wih[j * 3 + 0]);
        wih[r][1] = __ldg(&Wih[j * 3 + 1]);
        wih[r][2] = __ldg(&Wih[j * 3 + 2]);
        vbih[r] = __ldg(&bih[j]);
        vbhh[r] = __ldg(&bhh[j]);
    }
    const float wl0 = __ldg(&Wlin[lane]);
    const float wl1 = __ldg(&Wlin[lane + 32]);
    const float bl  = __ldg(&blin[0]);

    // Per-batch state in registers
    float e0[NB][T_IN], e1[NB][T_IN];   // encoder slice, dims lane / lane+32
    float h0[NB], h1[NB];               // hidden, dims lane / lane+32
    float L[NB][3];                     // last (replicated across lanes)

#pragma unroll
    for (int b = 0; b < NB; b++) {
        int gb = b0 + b;
        h0[b] = hid0[gb * 64 + lane];
        h1[b] = hid0[gb * 64 + lane + 32];
        L[b][0] = __ldg(&last[gb * 3 + 0]);
        L[b][1] = __ldg(&last[gb * 3 + 1]);
        L[b][2] = __ldg(&last[gb * 3 + 2]);
#pragma unroll
        for (int t = 0; t < T_IN; t++) {
            e0[b][t] = enc[(t * B + gb) * 64 + lane];
            e1[b][t] = enc[(t * B + gb) * 64 + lane + 32];
        }
    }

    float* myh = hsh + (w * NB) * H;
    const unsigned long long* W64 =
        reinterpret_cast<const unsigned long long*>(Wsh);

#pragma unroll 1
    for (int step = 0; step < T_OUT; step++) {
        // ---- attention (per batch element, serialized to bound registers) ----
#pragma unroll
        for (int b = 0; b < NB; b++) {
            float p[T_IN];
#pragma unroll
            for (int t = 0; t < T_IN; t++)
                p[t] = fmaf(e0[b][t], h0[b], e1[b][t] * h1[b]);
#pragma unroll
            for (int off = 16; off > 0; off >>= 1) {
#pragma unroll
                for (int t = 0; t < T_IN; t++)
                    p[t] += __shfl_xor_sync(FULLMASK, p[t], off);
            }
            float m = p[0];
#pragma unroll
            for (int t = 1; t < T_IN; t++) m = fmaxf(m, p[t]);
            float s = 0.0f;
#pragma unroll
            for (int t = 0; t < T_IN; t++) { p[t] = __expf(p[t] - m); s += p[t]; }
            float inv = __fdividef(1.0f, s);
            float c0 = 0.0f, c1 = 0.0f;
#pragma unroll
            for (int t = 0; t < T_IN; t++) {
                c0 = fmaf(p[t], e0[b][t], c0);
                c1 = fmaf(p[t], e1[b][t], c1);
            }
            h0[b] = fmaf(c0, inv, h0[b]);   // hidden += context
            h1[b] = fmaf(c1, inv, h1[b]);
        }

        // ---- stage hidden to SMEM for the matvec broadcast ----
#pragma unroll
        for (int b = 0; b < NB; b++) {
            myh[b * H + lane]      = h0[b];
            myh[b * H + lane + 32] = h1[b];
        }
        __syncwarp();

        // ---- gh = h @ W_hh^T  (packed f32x2 over k-pairs) ----
        unsigned long long acc[6][NB];
#pragma unroll
        for (int r = 0; r < 6; r++)
#pragma unroll
            for (int b = 0; b < NB; b++) acc[r][b] = 0ull;

#pragma unroll 4
        for (int k2 = 0; k2 < K2; k2++) {
            unsigned long long wv[6];
#pragma unroll
            for (int r = 0; r < 6; r++)
                wv[r] = W64[k2 * 192 + lane + 32 * r];
            unsigned long long hv[NB];
#pragma unroll
            for (int b = 0; b < NB; b++)
                hv[b] = *reinterpret_cast<const unsigned long long*>(
                            myh + b * H + 2 * k2);
#pragma unroll
            for (int r = 0; r < 6; r++)
#pragma unroll
                for (int b = 0; b < NB; b++)
                    ffma2(acc[r][b], wv[r], hv[b]);
        }

        // ---- gates + output ----
#pragma unroll
        for (int b = 0; b < NB; b++) {
            float gh[6], gi[6];
#pragma unroll
            for (int r = 0; r < 6; r++) {
                gh[r] = f2lo(acc[r][b]) + f2hi(acc[r][b]) + vbhh[r];
                gi[r] = fmaf(wih[r][0], L[b][0],
                        fmaf(wih[r][1], L[b][1],
                        fmaf(wih[r][2], L[b][2], vbih[r])));
            }
            // rows [0,64)=r gate (r=0,1), [64,128)=z (r=2,3), [128,192)=n (r=4,5)
            float rg0 = sigf(gi[0] + gh[0]);
            float rg1 = sigf(gi[1] + gh[1]);
            float zg0 = sigf(gi[2] + gh[2]);
            float zg1 = sigf(gi[3] + gh[3]);
            float ng0 = tanhfast(fmaf(rg0, gh[4], gi[4]));
            float ng1 = tanhfast(fmaf(rg1, gh[5], gi[5]));
            h0[b] = fmaf(zg0, h0[b] - ng0, ng0);   // (1-z)n + z h
            h1[b] = fmaf(zg1, h1[b] - ng1, ng1);

            // out = h @ W_lin^T + b_lin (warp allreduce)
            float o = fmaf(h0[b], wl0, h1[b] * wl1);
#pragma unroll
            for (int off = 16; off > 0; off >>= 1)
                o += __shfl_xor_sync(FULLMASK, o, off);
            o += bl;

            L[b][2] = L[b][1];
            L[b][1] = L[b][0];
            L[b][0] = o;
            if (lane == 0) out[(b0 + b) * T_OUT + step] = o;
        }
        __syncwarp();   // protect myh reads from next step's writes
    }
}

extern "C" void kernel_launch(void* const* d_in, const int* in_sizes, int n_in,
                              void* d_out, int out_size) {
    const float* enc  = (const float*)d_in[0];
    const float* hid0 = (const float*)d_in[1];
    const float* last = (const float*)d_in[2];
    const float* Wih  = (const float*)d_in[3];
    const float* Whh  = (const float*)d_in[4];
    const float* bih  = (const float*)d_in[5];
    const float* bhh  = (const float*)d_in[6];
    const float* Wlin = (const float*)d_in[7];
    const float* blin = (const float*)d_in[8];
    float* out = (float*)d_out;

    cudaFuncSetAttribute(decoder_kernel,
                         cudaFuncAttributeMaxDynamicSharedMemorySize,
                         SMEM_BYTES);

    dim3 grid(B / BPC);   // 4096 CTAs
    decoder_kernel<<<grid, THREADS, SMEM_BYTES>>>(
        enc, hid0, last, Wih, Whh, bih, bhh, Wlin, blin, out);
}

// round 6
// speedup vs baseline: 1.3746x; 1.3746x over previous
#include <cuda_runtime.h>

// Decoder: T_IN=12, B=65536, H=64, T_OUT=12, OVERLAP=3
// Phase-split design, 128 threads / 16 batches per CTA:
//   Phase A (attention+out): 8-lane group owns one batch, lane owns 8 dims.
//   Phase B (GRU matvec+gates): 2x2 (row-half x batch-group) warp split so
//   each warp reads only half of W_hh per step while serving 8 batches.
// Hidden flows through smem buffers hA (post-attention) / hG (post-gates).

#define FULLMASK 0xFFFFFFFFu

constexpr int T_IN  = 12;
constexpr int T_OUT = 12;
constexpr int Bz    = 65536;
constexpr int H     = 64;
constexpr int WARPS = 4;
constexpr int THREADS = WARPS * 32;
constexpr int BPC   = 16;            // batches per CTA
constexpr int K4    = 16;            // 16 float4 chunks over k=64

constexpr int W4_ELEMS = K4 * 192;   // 3072 float4 = 48KB
constexpr int SMEM_BYTES = W4_ELEMS * 16      // W
                         + BPC * H * 4        // hA
                         + BPC * H * 4        // hG
                         + BPC * 16;          // L (float4 per batch)

__device__ __forceinline__ void ffma2(unsigned long long& d,
                                      unsigned long long a,
                                      unsigned long long b) {
    asm("fma.rn.f32x2 %0, %1, %2, %0;" : "+l"(d) : "l"(a), "l"(b));
}
__device__ __forceinline__ float f2lo(unsigned long long v) {
    return __uint_as_float((unsigned)(v & 0xFFFFFFFFull));
}
__device__ __forceinline__ float f2hi(unsigned long long v) {
    return __uint_as_float((unsigned)(v >> 32));
}
__device__ __forceinline__ float sigf(float x) {
    return __fdividef(1.0f, 1.0f + __expf(-x));
}
__device__ __forceinline__ float tanhfast(float x) {
    return __fdividef(2.0f, 1.0f + __expf(-2.0f * x)) - 1.0f;
}
__device__ __forceinline__ float dot8(float4 a, float4 b, float4 c, float4 d) {
    float s = a.x * b.x;
    s = fmaf(a.y, b.y, s); s = fmaf(a.z, b.z, s); s = fmaf(a.w, b.w, s);
    s = fmaf(c.x, d.x, s); s = fmaf(c.y, d.y, s);
    s = fmaf(c.z, d.z, s); s = fmaf(c.w, d.w, s);
    return s;
}

__global__ void __launch_bounds__(THREADS, 2)
decoder_kernel(const float* __restrict__ enc,    // (12, B, 64)
               const float* __restrict__ hid0,   // (B, 64)
               const float* __restrict__ last,   // (B, 3)
               const float* __restrict__ Wih,    // (192, 3)
               const float* __restrict__ Whh,    // (192, 64)
               const float* __restrict__ bih,    // (192)
               const float* __restrict__ bhh,    // (192)
               const float* __restrict__ Wlin,   // (1, 64)
               const float* __restrict__ blin,   // (1)
               float* __restrict__ out)          // (B, 12)
{
    extern __shared__ float smem[];
    float4* W4sh = reinterpret_cast<float4*>(smem);          // [k4*192 + j]
    float*  hAsh = smem + W4_ELEMS * 4;                      // BPC*64 floats
    float*  hGsh = hAsh + BPC * H;                           // BPC*64 floats
    float4* Lsh  = reinterpret_cast<float4*>(hGsh + BPC * H);// BPC float4

    const int tid  = threadIdx.x;
    const int lane = tid & 31;
    const int w    = tid >> 5;
    const int cb0  = blockIdx.x * BPC;

    // ---- stage W_hh as float4 k-chunks: W4sh[k4*192 + j] = Whh[j][4k4..+3]
    const float4* Whh4 = reinterpret_cast<const float4*>(Whh);
    for (int i = tid; i < W4_ELEMS; i += THREADS) {
        int k4 = i / 192, j = i - k4 * 192;
        W4sh[i] = __ldg(&Whh4[j * 16 + k4]);
    }
    // ---- stage hG = hid0, Lsh = last
    const float4* hid04 = reinterpret_cast<const float4*>(hid0);
    float4* hG4 = reinterpret_cast<float4*>(hGsh);
    for (int i = tid; i < BPC * 16; i += THREADS)
        hG4[i] = __ldg(&hid04[cb0 * 16 + i]);
    if (tid < BPC) {
        int gb = cb0 + tid;
        Lsh[tid] = make_float4(__ldg(&last[gb * 3 + 0]),
                               __ldg(&last[gb * 3 + 1]),
                               __ldg(&last[gb * 3 + 2]), 0.0f);
    }

    // ---- Phase A identity: 8-lane group -> one batch, lane -> 8 dims
    const int sub = lane >> 3, lg = lane & 7;
    const int bA  = w * 4 + sub;          // CTA-local batch
    const int gbA = cb0 + bA;
    const float4* Wl4 = reinterpret_cast<const float4*>(Wlin);
    const float4 wl0 = __ldg(&Wl4[lg * 2]);
    const float4 wl1 = __ldg(&Wl4[lg * 2 + 1]);
    const float  bl  = __ldg(blin);

    // encoder slice in registers: 12 t x 8 dims = 24 float4 halves
    const float4* enc4 = reinterpret_cast<const float4*>(enc);
    float4 ev0[T_IN], ev1[T_IN];
#pragma unroll
    for (int t = 0; t < T_IN; t++) {
        int idx = (t * Bz + gbA) * 16 + lg * 2;
        ev0[t] = __ldg(&enc4[idx]);
        ev1[t] = __ldg(&enc4[idx + 1]);
    }

    // ---- Phase B identity: row-half q, batch-group of 8
    const int q   = (w >> 1) * 32;        // 0 or 32
    const int bb0 = (w & 1) * 8;          // 0 or 8
    float wr[3][3], bi3[3], bh3[3];
#pragma unroll
    for (int g = 0; g < 3; g++) {
        int j = 64 * g + q + lane;
        wr[g][0] = __ldg(&Wih[j * 3 + 0]);
        wr[g][1] = __ldg(&Wih[j * 3 + 1]);
        wr[g][2] = __ldg(&Wih[j * 3 + 2]);
        bi3[g] = __ldg(&bih[j]);
        bh3[g] = __ldg(&bhh[j]);
    }

    __syncthreads();

    float4* hA4 = reinterpret_cast<float4*>(hAsh);
    const ulonglong2* W2  = reinterpret_cast<const ulonglong2*>(W4sh);
    const ulonglong2* HA2 = reinterpret_cast<const ulonglong2*>(hAsh);

#pragma unroll 1
    for (int step = 0; step < T_OUT; step++) {
        // ================= Phase A: out(step-1) + attention =================
        float4 h0 = hG4[bA * 16 + lg * 2];
        float4 h1 = hG4[bA * 16 + lg * 2 + 1];

        if (step > 0) {
            float o = dot8(h0, wl0, h1, wl1);
            o += __shfl_xor_sync(FULLMASK, o, 4);
            o += __shfl_xor_sync(FULLMASK, o, 2);
            o += __shfl_xor_sync(FULLMASK, o, 1);
            o += bl;
            if (lg == 0) {
                float4 L = Lsh[bA];
                out[gbA * T_OUT + step - 1] = o;
                Lsh[bA] = make_float4(o, L.x, L.y, 0.0f);
            }
        }

        float p[T_IN];
#pragma unroll
        for (int t = 0; t < T_IN; t++)
            p[t] = dot8(ev0[t], h0, ev1[t], h1);
#pragma unroll
        for (int off = 4; off > 0; off >>= 1)
#pragma unroll
            for (int t = 0; t < T_IN; t++)
                p[t] += __shfl_xor_sync(FULLMASK, p[t], off);

        float m = p[0];
#pragma unroll
        for (int t = 1; t < T_IN; t++) m = fmaxf(m, p[t]);
        float s = 0.0f;
#pragma unroll
        for (int t = 0; t < T_IN; t++) { p[t] = __expf(p[t] - m); s += p[t]; }
        float inv = __fdividef(1.0f, s);

        float4 c0 = make_float4(0.f, 0.f, 0.f, 0.f);
        float4 c1 = make_float4(0.f, 0.f, 0.f, 0.f);
#pragma unroll
        for (int t = 0; t < T_IN; t++) {
            c0.x = fmaf(p[t], ev0[t].x, c0.x); c0.y = fmaf(p[t], ev0[t].y, c0.y);
            c0.z = fmaf(p[t], ev0[t].z, c0.z); c0.w = fmaf(p[t], ev0[t].w, c0.w);
            c1.x = fmaf(p[t], ev1[t].x, c1.x); c1.y = fmaf(p[t], ev1[t].y, c1.y);
            c1.z = fmaf(p[t], ev1[t].z, c1.z); c1.w = fmaf(p[t], ev1[t].w, c1.w);
        }
        h0.x = fmaf(c0.x, inv, h0.x); h0.y = fmaf(c0.y, inv, h0.y);
        h0.z = fmaf(c0.z, inv, h0.z); h0.w = fmaf(c0.w, inv, h0.w);
        h1.x = fmaf(c1.x, inv, h1.x); h1.y = fmaf(c1.y, inv, h1.y);
        h1.z = fmaf(c1.z, inv, h1.z); h1.w = fmaf(c1.w, inv, h1.w);

        hA4[bA * 16 + lg * 2]     = h0;
        hA4[bA * 16 + lg * 2 + 1] = h1;
        __syncthreads();

        // ============ Phase B: gh = hA @ W_hh^T (rows q..), gates ============
        unsigned long long acc[3][8];
#pragma unroll
        for (int g = 0; g < 3; g++)
#pragma unroll
            for (int b = 0; b < 8; b++) acc[g][b] = 0ull;

#pragma unroll 1
        for (int k4 = 0; k4 < K4; k4++) {
            ulonglong2 wv0 = W2[k4 * 192 + q + lane];
            ulonglong2 wv1 = W2[k4 * 192 + 64 + q + lane];
            ulonglong2 wv2 = W2[k4 * 192 + 128 + q + lane];
            ulonglong2 hv[8];
#pragma unroll
            for (int b = 0; b < 8; b++)
                hv[b] = HA2[(bb0 + b) * 16 + k4];
#pragma unroll
            for (int b = 0; b < 8; b++) {
                ffma2(acc[0][b], wv0.x, hv[b].x); ffma2(acc[0][b], wv0.y, hv[b].y);
                ffma2(acc[1][b], wv1.x, hv[b].x); ffma2(acc[1][b], wv1.y, hv[b].y);
                ffma2(acc[2][b], wv2.x, hv[b].x); ffma2(acc[2][b], wv2.y, hv[b].y);
            }
        }

#pragma unroll
        for (int b = 0; b < 8; b++) {
            float ghr = f2lo(acc[0][b]) + f2hi(acc[0][b]) + bh3[0];
            float ghz = f2lo(acc[1][b]) + f2hi(acc[1][b]) + bh3[1];
            float ghn = f2lo(acc[2][b]) + f2hi(acc[2][b]) + bh3[2];
            float4 L = Lsh[bb0 + b];
            float gir = fmaf(wr[0][0], L.x, fmaf(wr[0][1], L.y, fmaf(wr[0][2], L.z, bi3[0])));
            float giz = fmaf(wr[1][0], L.x, fmaf(wr[1][1], L.y, fmaf(wr[1][2], L.z, bi3[1])));
            float gin = fmaf(wr[2][0], L.x, fmaf(wr[2][1], L.y, fmaf(wr[2][2], L.z, bi3[2])));
            float r = sigf(gir + ghr);
            float z = sigf(giz + ghz);
            float n = tanhfast(fmaf(r, ghn, gin));
            float hp = hAsh[(bb0 + b) * H + q + lane];
            hGsh[(bb0 + b) * H + q + lane] = fmaf(z, hp - n, n);
        }
        __syncthreads();
    }

    // ---- final output (step T_OUT-1) from hG ----
    {
        float4 h0 = hG4[bA * 16 + lg * 2];
        float4 h1 = hG4[bA * 16 + lg * 2 + 1];
        float o = dot8(h0, wl0, h1, wl1);
        o += __shfl_xor_sync(FULLMASK, o, 4);
        o += __shfl_xor_sync(FULLMASK, o, 2);
        o += __shfl_xor_sync(FULLMASK, o, 1);
        o += bl;
        if (lg == 0) out[gbA * T_OUT + T_OUT - 1] = o;
    }
}

extern "C" void kernel_launch(void* const* d_in, const int* in_sizes, int n_in,
                              void* d_out, int out_size) {
    const float* enc  = (const float*)d_in[0];
    const float* hid0 = (const float*)d_in[1];
    const float* last = (const float*)d_in[2];
    const float* Wih  = (const float*)d_in[3];
    const float* Whh  = (const float*)d_in[4];
    const float* bih  = (const float*)d_in[5];
    const float* bhh  = (const float*)d_in[6];
    const float* Wlin = (const float*)d_in[7];
    const float* blin = (const float*)d_in[8];
    float* out = (float*)d_out;

    cudaFuncSetAttribute(decoder_kernel,
                         cudaFuncAttributeMaxDynamicSharedMemorySize,
                         SMEM_BYTES);

    dim3 grid(Bz / BPC);   // 4096 CTAs
    decoder_kernel<<<grid, THREADS, SMEM_BYTES>>>(
        enc, hid0, last, Wih, Whh, bih, bhh, Wlin, blin, out);
}